// round 13
// baseline (speedup 1.0000x reference)
#include <cuda_runtime.h>
#include <cuda_bf16.h>

// Problem constants (from reference)
#define BATCH  16
#define MCTRL  64
#define NCTRL  64
#define LKNOT  68      // M + P + 1
#define DEG    3
#define TOUT   256     // OUT_U == OUT_V
#define RPB    4       // u-rows per tile
#define TPB    4       // tiles per block -> 16 rows per block
#define THREADS 256
#define BPB    (TOUT / (RPB * TPB))   // 16 blocks per batch
#define UPAD   (LKNOT + 28)           // padded knots for branch-free bsearch

// Span binary search on padded array (U[i>=LKNOT] = +inf): reference's
// first-occurrence argmin over masked diffs equals the last index s with
// (traw - U[s+DEG] > thr), or 0 if none.
__device__ __forceinline__ int find_span(const float* __restrict__ U,
                                         float traw, float thr)
{
    int c = 0;
    #pragma unroll
    for (int step = 32; step >= 1; step >>= 1) {
        int nc = c + step;
        if ((traw - U[nc - 1 + DEG]) > thr) c = nc;   // pad => pred false
    }
    if (c > 62) c = 62;
    int bi = c - 1;
    if (bi < 0) bi = 0;
    int span = bi + DEG;
    if (span > MCTRL - 1) span = MCTRL - 1;
    return span;
}

// Degree-3 Cox-de Boor on raw (unnormalized) knots — affine invariant.
__device__ __forceinline__ float4 cox_de_boor(const float* __restrict__ U,
                                              float t, int span)
{
    float Nb[DEG + 1];
    Nb[0] = 1.f;
    #pragma unroll
    for (int k = 1; k <= DEG; k++) {
        float saved = 0.f;
        #pragma unroll
        for (int r = 0; r < DEG; r++) {
            if (r >= k) break;
            float K1   = U[span + r + 1];
            float K2   = U[span + 1 - k + r];
            float temp = __fdividef(Nb[r], (K1 - t) + (t - K2));
            Nb[r]  = saved + (K1 - t) * temp;
            saved  = (t - K2) * temp;
        }
        Nb[k] = saved;
    }
    return make_float4(Nb[0], Nb[1], Nb[2], Nb[3]);
}

// ---------------------------------------------------------------------------
// Fused tile-loop kernel. 256 blocks x 256 threads; each block: one prologue
// (scan + one cox per thread) then 4 software-pipelined tiles of 4 u-rows.
// Double-buffered cols -> one barrier per tile; ctrl loads for tile t+1 are
// issued before tile t's barrier and fly during tile t's phase 2.
// u and v parameter grids are identical (reference builds V from knot_u too).
// ---------------------------------------------------------------------------
__global__ __launch_bounds__(THREADS, 6) void SurfEval_fused_kernel(
    const float4* __restrict__ ctrl,   // [B][64][64] float4 (x,y,z,w)
    const float*  __restrict__ knot_u, // [B][68]
    float*        __restrict__ out)    // [B][256][256][3]
{
    const int b      = blockIdx.x / BPB;
    const int i_base = (blockIdx.x % BPB) * (RPB * TPB);
    const int tid    = threadIdx.x;
    const int lane   = tid & 31;
    const int wid    = tid >> 5;

    __shared__ float  U[UPAD];
    __shared__ float  warpsum[2];
    __shared__ float4 basis_sh[TOUT];          // 4 KB
    __shared__ int    span_sh[TOUT];           // 1 KB (span-3)
    __shared__ float4 cols4[2][RPB][NCTRL];    // 8 KB double-buffered

    // ---- parallel inclusive cumsum of the 68 raw knot increments ----
    {
        float v = (tid < LKNOT) ? knot_u[b * LKNOT + tid] : 0.f;
        #pragma unroll
        for (int off = 1; off < 32; off <<= 1) {
            float n = __shfl_up_sync(0xffffffffu, v, off);
            if (lane >= off) v += n;
        }
        if (lane == 31 && wid < 2) warpsum[wid] = v;
        if (tid >= LKNOT && tid < UPAD) U[tid] = __int_as_float(0x7f800000);
        __syncthreads();
        if (wid == 1)      v += warpsum[0];
        else if (wid == 2) v += warpsum[0] + warpsum[1];
        if (tid < LKNOT) U[tid] = v;
        __syncthreads();
    }

    const float c0  = U[0];
    const float den = U[LKNOT - 1] - c0;
    const float thr = 1e-8f * den;
    const float step01 = (float)((1.0 - 2e-5) / 255.0);

    const int ri = tid >> 6;            // 0..3 (phase-1 row within tile)
    const int cc = tid & 63;            // 0..63 (ctrl column)

    // ---- tile-0 row span (cheap recompute) -> issue first loads ASAP ----
    float4 p0, p1, p2, p3;
    {
        const int   i     = i_base + ri;
        const float t_row = c0 + fmaf((float)i, step01, 1e-5f) * den;
        const int   srow  = find_span(U, t_row, thr) - 3;
        const float4* cp  = ctrl + ((size_t)(b * MCTRL) + srow) * NCTRL + cc;
        p0 = cp[0 * NCTRL];
        p1 = cp[1 * NCTRL];
        p2 = cp[2 * NCTRL];
        p3 = cp[3 * NCTRL];
    }

    // ---- own (v-role) span + basis: the ONLY cox; publish ----
    const int   j     = tid;
    const float t_own = c0 + fmaf((float)j, step01, 1e-5f) * den;
    const int   sj    = find_span(U, t_own, thr) - 3;
    const float4 nv   = cox_de_boor(U, t_own, sj + 3);

    basis_sh[tid] = nv;
    span_sh[tid]  = sj;
    __syncthreads();   // publish barrier (tile-0 ctrl loads still in flight)

    // ---- software-pipelined tile loop ----
    #pragma unroll
    for (int t = 0; t < TPB; t++) {
        const int i0  = i_base + t * RPB;
        const int buf = t & 1;

        // phase 1: u-contraction for (row ri, ctrl column cc) of tile t
        {
            const float4 nu = basis_sh[i0 + ri];   // warp-uniform broadcast
            float4 r;
            r.x = fmaf(nu.x, p0.x, fmaf(nu.y, p1.x, fmaf(nu.z, p2.x, nu.w * p3.x)));
            r.y = fmaf(nu.x, p0.y, fmaf(nu.y, p1.y, fmaf(nu.z, p2.y, nu.w * p3.y)));
            r.z = fmaf(nu.x, p0.z, fmaf(nu.y, p1.z, fmaf(nu.z, p2.z, nu.w * p3.z)));
            r.w = 0.f;
            cols4[buf][ri][cc] = r;
        }

        // prefetch ctrl rows for tile t+1 (fly during this tile's phase 2)
        if (t + 1 < TPB) {
            const int srow = span_sh[i_base + (t + 1) * RPB + ri]; // broadcast
            const float4* cp = ctrl + ((size_t)(b * MCTRL) + srow) * NCTRL + cc;
            p0 = cp[0 * NCTRL];
            p1 = cp[1 * NCTRL];
            p2 = cp[2 * NCTRL];
            p3 = cp[3 * NCTRL];
        }

        __syncthreads();   // single barrier per tile: cols publish
        // (next tile's phase-1 writes go to the OTHER buffer; its previous
        //  readers finished before this barrier)

        // phase 2: v-contraction, RPB rows, direct streaming stores
        float* o = out + ((size_t)((b * TOUT) + i0) * TOUT + j) * 3;
        #pragma unroll
        for (int r = 0; r < RPB; r++) {
            float4 a  = cols4[buf][r][sj];
            float4 bb = cols4[buf][r][sj + 1];
            float4 cq = cols4[buf][r][sj + 2];
            float4 d  = cols4[buf][r][sj + 3];

            float x = fmaf(nv.x, a.x, fmaf(nv.y, bb.x, fmaf(nv.z, cq.x, nv.w * d.x)));
            float y = fmaf(nv.x, a.y, fmaf(nv.y, bb.y, fmaf(nv.z, cq.y, nv.w * d.y)));
            float z = fmaf(nv.x, a.z, fmaf(nv.y, bb.z, fmaf(nv.z, cq.z, nv.w * d.z)));

            __stcs(o + 0, x);
            __stcs(o + 1, y);
            __stcs(o + 2, z);
            o += (size_t)TOUT * 3;
        }
    }
}

// ---------------------------------------------------------------------------
// Launch. Inputs: d_in[0]=ctrl_pts [16,64,64,4] f32, d_in[1]=knot_u [16,68],
// d_in[2]=knot_v (UNUSED — reference builds V from knot_u).
// Output: [16,256,256,3] f32.
// ---------------------------------------------------------------------------
extern "C" void kernel_launch(void* const* d_in, const int* in_sizes, int n_in,
                              void* d_out, int out_size)
{
    const float4* ctrl   = (const float4*)d_in[0];
    const float*  knot_u = (const float*) d_in[1];
    float*        out    = (float*)d_out;

    SurfEval_fused_kernel<<<BATCH * BPB, THREADS>>>(ctrl, knot_u, out);
}